// round 1
// baseline (speedup 1.0000x reference)
#include <cuda_runtime.h>
#include <math.h>

#define BB 4
#define LL 512
#define VV 32128
#define AVV 32000
#define DD 768
#define NT (BB*LL)
#define NV4 (VV/4)     // 8032
#define ND4 (DD/4)     // 192

// Scratch (device globals; no allocation allowed)
__device__ int g_argmax[NT];
__device__ int g_psg[NT];   // >=0: psg token id to add (W[id]); -1: none

// ---------------------------------------------------------------------------
// Kernel A: per-batch psg index prep (exact reference semantics, tiny)
// ---------------------------------------------------------------------------
__global__ void psg_prep_kernel(const int* __restrict__ rwrt,
                                const int* __restrict__ psg_in) {
    __shared__ int sh[LL];
    const int b = blockIdx.x;
    const int l = threadIdx.x;
    const int* r = rwrt + b * LL;
    const int* p = psg_in + b * LL;

    // shifts = sum(rwrt == 1)
    sh[l] = (r[l] == 1) ? 1 : 0;
    __syncthreads();
    for (int s = LL / 2; s > 0; s >>= 1) {
        if (l < s) sh[l] += sh[l + s];
        __syncthreads();
    }
    const int shift = sh[0];
    __syncthreads();

    // trunc_ids[l] = extr_psg[(l - shift) mod L]
    int pos = ((l - shift) % LL + LL) % LL;
    int fm = 1 - r[LL - 1 - pos];                  // 1 - fliplr(rwrt)
    int psv = (pos == 0) ? 1 : p[pos - 1];         // roll(psg,1), [0]=1
    int trunc = fm * psv;

    // flag = cumsum(trunc != 0) > 0  <=>  l >= first nonzero index
    sh[l] = (trunc != 0) ? l : LL;
    __syncthreads();
    for (int s = LL / 2; s > 0; s >>= 1) {
        if (l < s) sh[l] = min(sh[l], sh[l + s]);
        __syncthreads();
    }
    const int firstnz = sh[0];

    g_psg[b * LL + l] = (l >= firstnz) ? trunc : -1;
}

// ---------------------------------------------------------------------------
// Kernel B: per-token argmax over V of logits + gumbel(g).  HBM-bound.
// ---------------------------------------------------------------------------
__device__ __forceinline__ float coarse_key(float lo, float u) {
    // t = -log(u), with series path near u=1 where __logf's absolute error
    // would destroy relative accuracy of tiny t (these are the winners!).
    float t;
    if (u > 0.99609375f) {
        float w = 1.0f - u;                        // exact (Sterbenz)
        t = fmaf(0.5f * w, w, w);                  // w + w^2/2, rel err <= w^2/3
    } else {
        t = -__logf(u);
    }
    return lo - __logf(t);                          // logits + (-log(t))
}

__device__ __forceinline__ double precise_key(float lo, float u) {
    double du = (double)u;
    return (double)lo - log(-log(du));
}

__device__ __forceinline__ void top2_insert(float w, int j,
                                            float& v1, int& i1,
                                            float& v2, int& i2) {
    if (w > v1 || (w == v1 && j < i1)) {
        v2 = v1; i2 = i1; v1 = w; i1 = j;
    } else if (w > v2 || (w == v2 && j < i2)) {
        v2 = w; i2 = j;
    }
}

__global__ void __launch_bounds__(256)
gumbel_argmax_kernel(const float* __restrict__ logits,
                     const float* __restrict__ gu) {
    const int t = blockIdx.x;
    const float4* lg = (const float4*)(logits + (size_t)t * VV);
    const float4* gg = (const float4*)(gu + (size_t)t * VV);

    float v1 = -INFINITY, v2 = -INFINITY;
    int i1 = 0, i2 = 1;

#pragma unroll 4
    for (int i = threadIdx.x; i < NV4; i += 256) {
        float4 a = lg[i];
        float4 b = gg[i];
        float k0 = coarse_key(a.x, b.x);
        float k1 = coarse_key(a.y, b.y);
        float k2 = coarse_key(a.z, b.z);
        float k3 = coarse_key(a.w, b.w);
        int base = 4 * i;
        top2_insert(k0, base + 0, v1, i1, v2, i2);
        top2_insert(k1, base + 1, v1, i1, v2, i2);
        top2_insert(k2, base + 2, v1, i1, v2, i2);
        top2_insert(k3, base + 3, v1, i1, v2, i2);
    }

    __shared__ float sv1[256], sv2[256];
    __shared__ int si1[256], si2[256];
    sv1[threadIdx.x] = v1; si1[threadIdx.x] = i1;
    sv2[threadIdx.x] = v2; si2[threadIdx.x] = i2;
    __syncthreads();

    for (int s = 128; s > 0; s >>= 1) {
        if (threadIdx.x < s) {
            float w1 = sv1[threadIdx.x + s], w2 = sv2[threadIdx.x + s];
            int   j1 = si1[threadIdx.x + s], j2 = si2[threadIdx.x + s];
            float a1 = sv1[threadIdx.x], a2 = sv2[threadIdx.x];
            int   b1 = si1[threadIdx.x], b2 = si2[threadIdx.x];
            top2_insert(w1, j1, a1, b1, a2, b2);
            top2_insert(w2, j2, a1, b1, a2, b2);
            sv1[threadIdx.x] = a1; si1[threadIdx.x] = b1;
            sv2[threadIdx.x] = a2; si2[threadIdx.x] = b2;
        }
        __syncthreads();
    }

    if (threadIdx.x == 0) {
        int w1 = si1[0], w2 = si2[0];
        int win = w1;
        if (sv1[0] - sv2[0] < 0.02f) {
            // near-tie: re-decide in fp64 (coarse key err bound ~1.1e-4 << 0.02)
            double k1 = precise_key(logits[(size_t)t * VV + w1],
                                    gu[(size_t)t * VV + w1]);
            double k2 = precise_key(logits[(size_t)t * VV + w2],
                                    gu[(size_t)t * VV + w2]);
            if (k2 > k1 || (k2 == k1 && w2 < w1)) win = w2;
        }
        g_argmax[t] = win;
    }
}

// ---------------------------------------------------------------------------
// Kernel C: out[t,:] = (rwrt && argmax<AV ? W[argmax] : 0) + (psg>=0 ? W[psg] : 0)
// ---------------------------------------------------------------------------
__global__ void __launch_bounds__(ND4)
assemble_kernel(const int* __restrict__ rwrt,
                const float* __restrict__ W,
                float* __restrict__ out) {
    const int t = blockIdx.x;
    const int d = threadIdx.x;  // 0..191 (float4 lanes)
    const float4* W4 = (const float4*)W;

    int am = g_argmax[t];
    bool use_a = (rwrt[t] != 0) && (am < AVV);
    int ps = g_psg[t];

    float4 acc = make_float4(0.f, 0.f, 0.f, 0.f);
    if (use_a) acc = W4[(size_t)am * ND4 + d];
    if (ps >= 0) {
        float4 w = W4[(size_t)ps * ND4 + d];
        acc.x += w.x; acc.y += w.y; acc.z += w.z; acc.w += w.w;
    }
    ((float4*)out)[(size_t)t * ND4 + d] = acc;
}

// ---------------------------------------------------------------------------
extern "C" void kernel_launch(void* const* d_in, const int* in_sizes, int n_in,
                              void* d_out, int out_size) {
    const float* logits = (const float*)d_in[0];
    const float* gu     = (const float*)d_in[1];
    const float* W      = (const float*)d_in[2];
    const int*   rwrt   = (const int*)d_in[3];
    const int*   psg    = (const int*)d_in[4];
    float* out = (float*)d_out;

    psg_prep_kernel<<<BB, LL>>>(rwrt, psg);
    gumbel_argmax_kernel<<<NT, 256>>>(logits, gu);
    assemble_kernel<<<NT, ND4>>>(rwrt, W, out);
}

// round 2
// speedup vs baseline: 1.2074x; 1.2074x over previous
#include <cuda_runtime.h>
#include <math.h>

#define BB 4
#define LL 512
#define VV 32128
#define AVV 32000
#define DD 768
#define NT (BB*LL)
#define NV4 (VV/4)     // 8032
#define ND4 (DD/4)     // 192
#define NTH 256

// ---------------------------------------------------------------------------
// Coarse key: logits - log(-log u), branchless.
// Near u=1, -log u is tiny and __logf's ~3.6e-7 ABSOLUTE error would blow up
// the relative error of t (these are exactly the winning tokens). Series path
// via exact w = 1-u (Sterbenz) bounds coarse key abs error <= ~1.1e-4.
// ---------------------------------------------------------------------------
__device__ __forceinline__ float coarse_key(float lo, float u) {
    float w  = 1.0f - u;                 // exact for u > 0.5
    float ts = fmaf(0.5f * w, w, w);     // w + w^2/2
    float tl = -__logf(u);
    float t  = (u > 0.99609375f) ? ts : tl;
    return lo - __logf(t);
}

__device__ __forceinline__ double precise_key(float lo, float u) {
    return (double)lo - log(-log((double)u));
}

// Tie-breaking insert (used only in the small block reduction)
__device__ __forceinline__ void top2_insert(float w, int j,
                                            float& v1, int& i1,
                                            float& v2, int& i2) {
    if (w > v1 || (w == v1 && j < i1)) {
        v2 = v1; i2 = i1; v1 = w; i1 = j;
    } else if (w > v2 || (w == v2 && j < i2)) {
        v2 = w; i2 = j;
    }
}

// ---------------------------------------------------------------------------
// ONE fused kernel: per-token block (2048 blocks x 256 threads)
//   phase 0: recompute per-batch psg info (shift, firstnz) from 512-int rows
//   phase 1: stream 2 x 128.5KB (logits+gumbel), branchless top-2 argmax
//   phase 2: block reduce, fp64 near-tie recheck
//   phase 3: gather W rows, write D=768 output
// ---------------------------------------------------------------------------
__global__ void __launch_bounds__(NTH)
fused_kernel(const float* __restrict__ logits,
             const float* __restrict__ gu,
             const float* __restrict__ W,
             const int*   __restrict__ rwrt,
             const int*   __restrict__ psg_in,
             float*       __restrict__ out) {
    const int t   = blockIdx.x;
    const int b   = t / LL;
    const int l   = t % LL;
    const int tid = threadIdx.x;

    __shared__ int   s_i[NTH];
    __shared__ float s_v1[NTH]; __shared__ int s_i1[NTH];
    __shared__ float s_v2[NTH]; __shared__ int s_i2[NTH];
    __shared__ int   s_res[2];          // [0]=winning argmax, [1]=psg id (-1 none)

    const int* r = rwrt   + b * LL;
    const int* p = psg_in + b * LL;

    // ---- phase 0a: shift = sum(rwrt == 1) over the row ----
    s_i[tid] = (r[tid] == 1) + (r[tid + NTH] == 1);
    __syncthreads();
    for (int s = NTH / 2; s > 0; s >>= 1) {
        if (tid < s) s_i[tid] += s_i[tid + s];
        __syncthreads();
    }
    const int shift = s_i[0];
    __syncthreads();

    // ---- phase 0b: firstnz = min l'' with trunc(pos(l'')) != 0 ----
    int cand = LL;
#pragma unroll
    for (int k = 0; k < 2; k++) {
        int ll  = tid + k * NTH;
        int pos = ((ll - shift) % LL + LL) % LL;
        int fm  = 1 - r[LL - 1 - pos];              // 1 - fliplr(rwrt)
        int psv = (pos == 0) ? 1 : p[pos - 1];      // roll(psg,1), [0]=1
        if (fm * psv != 0) cand = min(cand, ll);
    }
    s_i[tid] = cand;
    __syncthreads();
    for (int s = NTH / 2; s > 0; s >>= 1) {
        if (tid < s) s_i[tid] = min(s_i[tid], s_i[tid + s]);
        __syncthreads();
    }
    const int firstnz = s_i[0];

    // own token's psg id (flag true => W[trunc], even when trunc == 0)
    int ps;
    {
        int pos   = ((l - shift) % LL + LL) % LL;
        int fm    = 1 - r[LL - 1 - pos];
        int psv   = (pos == 0) ? 1 : p[pos - 1];
        int trunc = fm * psv;
        ps = (l >= firstnz) ? trunc : -1;
    }

    // ---- phase 1: streaming branchless top-2 over V ----
    const float4* lg = (const float4*)(logits + (size_t)t * VV);
    const float4* gg = (const float4*)(gu     + (size_t)t * VV);

    float v1 = -INFINITY, v2 = -INFINITY;
    int   i1 = 0,         i2 = 1;

#pragma unroll 4
    for (int i = tid; i < NV4; i += NTH) {
        float4 a = __ldcs(lg + i);
        float4 g = __ldcs(gg + i);
        float k0 = coarse_key(a.x, g.x);
        float k1 = coarse_key(a.y, g.y);
        float k2 = coarse_key(a.z, g.z);
        float k3 = coarse_key(a.w, g.w);
        int base = 4 * i;
#pragma unroll
        for (int e = 0; e < 4; e++) {
            float k = (e == 0) ? k0 : (e == 1) ? k1 : (e == 2) ? k2 : k3;
            int   j = base + e;
            // branchless: strict '>' keeps earliest index within a thread
            bool gt1 = k > v1;
            bool gt2 = k > v2;
            float nv2 = gt1 ? v1 : (gt2 ? k : v2);
            int   ni2 = gt1 ? i1 : (gt2 ? j : i2);
            v1 = gt1 ? k : v1;
            i1 = gt1 ? j : i1;
            v2 = nv2; i2 = ni2;
        }
    }

    // ---- phase 2: block reduction ----
    s_v1[tid] = v1; s_i1[tid] = i1;
    s_v2[tid] = v2; s_i2[tid] = i2;
    __syncthreads();
    for (int s = NTH / 2; s > 0; s >>= 1) {
        if (tid < s) {
            float w1 = s_v1[tid + s], w2 = s_v2[tid + s];
            int   j1 = s_i1[tid + s], j2 = s_i2[tid + s];
            float a1 = s_v1[tid],     a2 = s_v2[tid];
            int   c1 = s_i1[tid],     c2 = s_i2[tid];
            top2_insert(w1, j1, a1, c1, a2, c2);
            top2_insert(w2, j2, a1, c1, a2, c2);
            s_v1[tid] = a1; s_i1[tid] = c1;
            s_v2[tid] = a2; s_i2[tid] = c2;
        }
        __syncthreads();
    }

    if (tid == 0) {
        int w1 = s_i1[0], w2 = s_i2[0];
        int win = w1;
        if (s_v1[0] - s_v2[0] < 0.02f) {
            // near-tie: fp64 re-decide (coarse err bound ~1.1e-4 << 0.02)
            double k1 = precise_key(logits[(size_t)t * VV + w1],
                                    gu[(size_t)t * VV + w1]);
            double k2 = precise_key(logits[(size_t)t * VV + w2],
                                    gu[(size_t)t * VV + w2]);
            if (k2 > k1 || (k2 == k1 && w2 < w1)) win = w2;
        }
        s_res[0] = win;
        s_res[1] = ps;   // same value in all threads; write from t0
    }
    __syncthreads();

    // ---- phase 3: output = (rwrt && am<AV ? W[am] : 0) + (ps>=0 ? W[ps] : 0) ----
    if (tid < ND4) {
        const float4* W4 = (const float4*)W;
        int  am    = s_res[0];
        int  psx   = s_res[1];
        bool use_a = (r[l] != 0) && (am < AVV);

        float4 acc = make_float4(0.f, 0.f, 0.f, 0.f);
        if (use_a) acc = W4[(size_t)am * ND4 + tid];
        if (psx >= 0) {
            float4 w = W4[(size_t)psx * ND4 + tid];
            acc.x += w.x; acc.y += w.y; acc.z += w.z; acc.w += w.w;
        }
        ((float4*)out)[(size_t)t * ND4 + tid] = acc;
    }
}

// ---------------------------------------------------------------------------
extern "C" void kernel_launch(void* const* d_in, const int* in_sizes, int n_in,
                              void* d_out, int out_size) {
    const float* logits = (const float*)d_in[0];
    const float* gu     = (const float*)d_in[1];
    const float* W      = (const float*)d_in[2];
    const int*   rwrt   = (const int*)d_in[3];
    const int*   psg    = (const int*)d_in[4];
    float* out = (float*)d_out;

    fused_kernel<<<NT, NTH>>>(logits, gu, W, rwrt, psg, out);
}

// round 3
// speedup vs baseline: 1.2836x; 1.0631x over previous
#include <cuda_runtime.h>
#include <math.h>

#define BB 4
#define LL 512
#define VV 32128
#define AVV 32000
#define DD 768
#define NT (BB*LL)
#define NV4 (VV/4)      // 8032
#define ND4 (DD/4)      // 192
#define NTH 256
#define CH 4            // chunks per token
#define CV4 (NV4/CH)    // 2008 float4 per chunk

// Partial top-2 per (token, chunk): {bits(v1), i1, bits(v2), i2}
__device__ int4 g_part[NT * CH];

// ---------------------------------------------------------------------------
// Exact coarse key: lo - log(-log u), with series path near u=1 (the winners:
// max-gumbel has u ~ 1 - 3e-5, where __logf's ~1e-6 ABSOLUTE error would be
// catastrophic relative error on t). Abs key error bounded ~1.2e-4.
// ---------------------------------------------------------------------------
__device__ __forceinline__ float coarse_key(float lo, float u) {
    float w  = 1.0f - u;                 // exact for u > 0.5 (Sterbenz)
    float ts = fmaf(0.5f * w, w, w);     // w + w^2/2
    float tl = -__logf(u);
    float t  = (u > 0.99609375f) ? ts : tl;
    return lo - __logf(t);
}

__device__ __forceinline__ double precise_key(float lo, float u) {
    return (double)lo - log(-log((double)u));
}

// Exact within-thread top-2 insert (displacement form; strict '>' keeps
// earliest index).  Every rejected/displaced value is a v2 candidate, so
// (v1,v2) is the exact top-2 of all inserted elements.
__device__ __forceinline__ void ins2(float k, int j,
                                     float& v1, int& i1,
                                     float& v2, int& i2) {
    bool p = k > v1;
    float dv = p ? v1 : k;
    int   di = p ? i1 : j;
    if (p) { v1 = k; i1 = j; }
    if (dv > v2) { v2 = dv; i2 = di; }
}

// Tie-breaking merge insert (cross-thread/cross-chunk: prefer lower index)
__device__ __forceinline__ void top2_insert(float w, int j,
                                            float& v1, int& i1,
                                            float& v2, int& i2) {
    if (w > v1 || (w == v1 && j < i1)) {
        v2 = v1; i2 = i1; v1 = w; i1 = j;
    } else if (w > v2 || (w == v2 && j < i2)) {
        v2 = w; i2 = j;
    }
}

// ---------------------------------------------------------------------------
// K1: streaming scan.  grid = NT*CH blocks, each handles CV4 float4 of one
// token.  Cheap UB filter; exact key only when ub > thr (thr <= global #2).
// ---------------------------------------------------------------------------
__global__ void __launch_bounds__(NTH)
scan_kernel(const float* __restrict__ logits,
            const float* __restrict__ gu) {
    const int blk = blockIdx.x;
    const int t   = blk >> 2;
    const int c   = blk & 3;
    const int tid = threadIdx.x;

    const float4* lg = (const float4*)(logits + (size_t)t * VV) + c * CV4;
    const float4* gg = (const float4*)(gu     + (size_t)t * VV) + c * CV4;
    const int jbase = c * CV4 * 4;

    float v1 = -INFINITY, v2 = -INFINITY;
    int   i1 = 0,         i2 = 1;

    // ---- seed: one exact element per lane, warp-wide 2nd-max -> thr ----
    {
        float4 a = __ldcs(lg + tid);
        float4 g = __ldcs(gg + tid);
        int base = jbase + 4 * tid;
        ins2(coarse_key(a.x, g.x), base + 0, v1, i1, v2, i2);
        ins2(coarse_key(a.y, g.y), base + 1, v1, i1, v2, i2);
        ins2(coarse_key(a.z, g.z), base + 2, v1, i1, v2, i2);
        ins2(coarse_key(a.w, g.w), base + 3, v1, i1, v2, i2);
    }
    // warp top-2 of values only (real element values => <= global #2)
    float sa = v1, sb = v2;
#pragma unroll
    for (int off = 16; off > 0; off >>= 1) {
        float oa = __shfl_xor_sync(0xFFFFFFFFu, sa, off);
        float ob = __shfl_xor_sync(0xFFFFFFFFu, sb, off);
        float hi = fmaxf(sa, oa);
        float lo2 = fmaxf(fminf(sa, oa), fmaxf(sb, ob));
        sa = hi; sb = lo2;
    }
    float thr = fmaxf(v2, sb);   // provable lower bound on global #2

    // ---- main filtered scan ----
    const float CB  = 88.029693f;       // 127 * ln2
    const float CC  = 8.2629582e-8f;    // ln2 / 2^23
    const float EPS = 1e-5f;            // I2F rounding margin

    for (int i = tid + NTH; i < CV4; i += NTH) {
        float4 a = __ldcs(lg + i);
        float4 g = __ldcs(gg + i);
        // one-sided bit-log upper bound: key <= lo - ln2*l2a(1-u)
        float ub0 = fmaf(-CC, (float)__float_as_int(1.0f - g.x), a.x + CB + EPS);
        float ub1 = fmaf(-CC, (float)__float_as_int(1.0f - g.y), a.y + CB + EPS);
        float ub2 = fmaf(-CC, (float)__float_as_int(1.0f - g.z), a.z + CB + EPS);
        float ub3 = fmaf(-CC, (float)__float_as_int(1.0f - g.w), a.w + CB + EPS);
        if (ub0 > thr || ub1 > thr || ub2 > thr || ub3 > thr) {
            int base = jbase + 4 * i;
            ins2(coarse_key(a.x, g.x), base + 0, v1, i1, v2, i2);
            ins2(coarse_key(a.y, g.y), base + 1, v1, i1, v2, i2);
            ins2(coarse_key(a.z, g.z), base + 2, v1, i1, v2, i2);
            ins2(coarse_key(a.w, g.w), base + 3, v1, i1, v2, i2);
            thr = fmaxf(thr, v2);
        }
    }

    // ---- block reduction (exact top-2 with index tie-break) ----
    __shared__ float s_v1[NTH]; __shared__ int s_i1[NTH];
    __shared__ float s_v2[NTH]; __shared__ int s_i2[NTH];
    s_v1[tid] = v1; s_i1[tid] = i1;
    s_v2[tid] = v2; s_i2[tid] = i2;
    __syncthreads();
    for (int s = NTH / 2; s > 0; s >>= 1) {
        if (tid < s) {
            float w1 = s_v1[tid + s], w2 = s_v2[tid + s];
            int   j1 = s_i1[tid + s], j2 = s_i2[tid + s];
            float a1 = s_v1[tid],     a2 = s_v2[tid];
            int   c1 = s_i1[tid],     c2 = s_i2[tid];
            top2_insert(w1, j1, a1, c1, a2, c2);
            top2_insert(w2, j2, a1, c1, a2, c2);
            s_v1[tid] = a1; s_i1[tid] = c1;
            s_v2[tid] = a2; s_i2[tid] = c2;
        }
        __syncthreads();
    }
    if (tid == 0) {
        g_part[blk] = make_int4(__float_as_int(s_v1[0]), s_i1[0],
                                __float_as_int(s_v2[0]), s_i2[0]);
    }
}

// ---------------------------------------------------------------------------
// K2: merge partials + fp64 near-tie recheck + psg logic + W gather
// ---------------------------------------------------------------------------
__global__ void __launch_bounds__(NTH)
finish_kernel(const float* __restrict__ logits,
              const float* __restrict__ gu,
              const float* __restrict__ W,
              const int*   __restrict__ rwrt,
              const int*   __restrict__ psg_in,
              float*       __restrict__ out) {
    const int t   = blockIdx.x;
    const int b   = t / LL;
    const int l   = t % LL;
    const int tid = threadIdx.x;

    __shared__ int s_i[NTH];
    __shared__ int s_res[2];   // [0]=argmax, [1]=psg id (-1 none)

    const int* r = rwrt   + b * LL;
    const int* p = psg_in + b * LL;

    // shift = sum(rwrt == 1)
    s_i[tid] = (r[tid] == 1) + (r[tid + NTH] == 1);
    __syncthreads();
    for (int s = NTH / 2; s > 0; s >>= 1) {
        if (tid < s) s_i[tid] += s_i[tid + s];
        __syncthreads();
    }
    const int shift = s_i[0];
    __syncthreads();

    // firstnz over trunc ids
    int cand = LL;
#pragma unroll
    for (int k = 0; k < 2; k++) {
        int ll  = tid + k * NTH;
        int pos = ((ll - shift) % LL + LL) % LL;
        int fm  = 1 - r[LL - 1 - pos];
        int psv = (pos == 0) ? 1 : p[pos - 1];
        if (fm * psv != 0) cand = min(cand, ll);
    }
    s_i[tid] = cand;
    __syncthreads();
    for (int s = NTH / 2; s > 0; s >>= 1) {
        if (tid < s) s_i[tid] = min(s_i[tid], s_i[tid + s]);
        __syncthreads();
    }
    const int firstnz = s_i[0];

    if (tid == 0) {
        // own token's psg id
        int pos   = ((l - shift) % LL + LL) % LL;
        int fm    = 1 - r[LL - 1 - pos];
        int psv   = (pos == 0) ? 1 : p[pos - 1];
        int trunc = fm * psv;
        s_res[1] = (l >= firstnz) ? trunc : -1;

        // merge 4 chunk partials
        float v1 = -INFINITY, v2 = -INFINITY;
        int   i1 = 0,         i2 = 1;
#pragma unroll
        for (int cc = 0; cc < CH; cc++) {
            int4 pr = g_part[t * CH + cc];
            top2_insert(__int_as_float(pr.x), pr.y, v1, i1, v2, i2);
            top2_insert(__int_as_float(pr.z), pr.w, v1, i1, v2, i2);
        }
        int win = i1;
        if (v1 - v2 < 0.02f) {
            double k1 = precise_key(logits[(size_t)t * VV + i1],
                                    gu[(size_t)t * VV + i1]);
            double k2 = precise_key(logits[(size_t)t * VV + i2],
                                    gu[(size_t)t * VV + i2]);
            if (k2 > k1 || (k2 == k1 && i2 < i1)) win = i2;
        }
        s_res[0] = win;
    }
    __syncthreads();

    // output = (rwrt && am<AV ? W[am] : 0) + (ps>=0 ? W[ps] : 0)
    if (tid < ND4) {
        const float4* W4 = (const float4*)W;
        int  am    = s_res[0];
        int  psx   = s_res[1];
        bool use_a = (r[l] != 0) && (am < AVV);

        float4 acc = make_float4(0.f, 0.f, 0.f, 0.f);
        if (use_a) acc = W4[(size_t)am * ND4 + tid];
        if (psx >= 0) {
            float4 w = W4[(size_t)psx * ND4 + tid];
            acc.x += w.x; acc.y += w.y; acc.z += w.z; acc.w += w.w;
        }
        ((float4*)out)[(size_t)t * ND4 + tid] = acc;
    }
}

// ---------------------------------------------------------------------------
extern "C" void kernel_launch(void* const* d_in, const int* in_sizes, int n_in,
                              void* d_out, int out_size) {
    const float* logits = (const float*)d_in[0];
    const float* gu     = (const float*)d_in[1];
    const float* W      = (const float*)d_in[2];
    const int*   rwrt   = (const int*)d_in[3];
    const int*   psg    = (const int*)d_in[4];
    float* out = (float*)d_out;

    scan_kernel<<<NT * CH, NTH>>>(logits, gu);
    finish_kernel<<<NT, NTH>>>(logits, gu, W, rwrt, psg, out);
}

// round 4
// speedup vs baseline: 1.3068x; 1.0181x over previous
#include <cuda_runtime.h>
#include <math.h>

#define BB 4
#define LL 512
#define VV 32128
#define AVV 32000
#define DD 768
#define NT (BB*LL)
#define NV4 (VV/4)      // 8032
#define ND4 (DD/4)      // 192
#define NTH 256
#define CH 4            // chunks per token
#define CV4 (NV4/CH)    // 2008 float4 per chunk
#define TPB 8           // tokens per finish block

// Partial top-2 per (token, chunk): {bits(v1), i1, bits(v2), i2}
__device__ int4 g_part[NT * CH];

// ---------------------------------------------------------------------------
// Exact coarse key: lo - log(-log u), with series path near u=1 (the winners:
// max-gumbel has u ~ 1 - 3e-5, where __logf's ~1e-6 ABSOLUTE error would be
// catastrophic relative error on t). Abs key error bounded ~1.2e-4.
// ---------------------------------------------------------------------------
__device__ __forceinline__ float coarse_key(float lo, float u) {
    float w  = 1.0f - u;                 // exact for u > 0.5 (Sterbenz)
    float ts = fmaf(0.5f * w, w, w);     // w + w^2/2
    float tl = -__logf(u);
    float t  = (u > 0.99609375f) ? ts : tl;
    return lo - __logf(t);
}

__device__ __forceinline__ double precise_key(float lo, float u) {
    return (double)lo - log(-log((double)u));
}

// Exact within-thread top-2 insert (displacement form; strict '>' keeps
// earliest index).
__device__ __forceinline__ void ins2(float k, int j,
                                     float& v1, int& i1,
                                     float& v2, int& i2) {
    bool p = k > v1;
    float dv = p ? v1 : k;
    int   di = p ? i1 : j;
    if (p) { v1 = k; i1 = j; }
    if (dv > v2) { v2 = dv; i2 = di; }
}

// Tie-breaking merge insert (cross-thread/cross-chunk: prefer lower index)
__device__ __forceinline__ void top2_insert(float w, int j,
                                            float& v1, int& i1,
                                            float& v2, int& i2) {
    if (w > v1 || (w == v1 && j < i1)) {
        v2 = v1; i2 = i1; v1 = w; i1 = j;
    } else if (w > v2 || (w == v2 && j < i2)) {
        v2 = w; i2 = j;
    }
}

// ---------------------------------------------------------------------------
// K1: streaming scan (unchanged from R3 — runs at ~6.4 TB/s, near roofline).
// grid = NT*CH blocks; cheap bit-log UB filter, exact key only on survivors.
// ---------------------------------------------------------------------------
__global__ void __launch_bounds__(NTH)
scan_kernel(const float* __restrict__ logits,
            const float* __restrict__ gu) {
    const int blk = blockIdx.x;
    const int t   = blk >> 2;
    const int c   = blk & 3;
    const int tid = threadIdx.x;

    const float4* lg = (const float4*)(logits + (size_t)t * VV) + c * CV4;
    const float4* gg = (const float4*)(gu     + (size_t)t * VV) + c * CV4;
    const int jbase = c * CV4 * 4;

    float v1 = -INFINITY, v2 = -INFINITY;
    int   i1 = 0,         i2 = 1;

    // seed: one exact float4 per lane, warp-wide 2nd-max -> thr
    {
        float4 a = __ldcs(lg + tid);
        float4 g = __ldcs(gg + tid);
        int base = jbase + 4 * tid;
        ins2(coarse_key(a.x, g.x), base + 0, v1, i1, v2, i2);
        ins2(coarse_key(a.y, g.y), base + 1, v1, i1, v2, i2);
        ins2(coarse_key(a.z, g.z), base + 2, v1, i1, v2, i2);
        ins2(coarse_key(a.w, g.w), base + 3, v1, i1, v2, i2);
    }
    float sa = v1, sb = v2;
#pragma unroll
    for (int off = 16; off > 0; off >>= 1) {
        float oa = __shfl_xor_sync(0xFFFFFFFFu, sa, off);
        float ob = __shfl_xor_sync(0xFFFFFFFFu, sb, off);
        float hi  = fmaxf(sa, oa);
        float lo2 = fmaxf(fminf(sa, oa), fmaxf(sb, ob));
        sa = hi; sb = lo2;
    }
    float thr = fmaxf(v2, sb);   // provable lower bound on global #2

    const float CB  = 88.029693f;       // 127 * ln2
    const float CC  = 8.2629582e-8f;    // ln2 / 2^23
    const float EPS = 1e-5f;            // I2F rounding margin

    for (int i = tid + NTH; i < CV4; i += NTH) {
        float4 a = __ldcs(lg + i);
        float4 g = __ldcs(gg + i);
        float ub0 = fmaf(-CC, (float)__float_as_int(1.0f - g.x), a.x + CB + EPS);
        float ub1 = fmaf(-CC, (float)__float_as_int(1.0f - g.y), a.y + CB + EPS);
        float ub2 = fmaf(-CC, (float)__float_as_int(1.0f - g.z), a.z + CB + EPS);
        float ub3 = fmaf(-CC, (float)__float_as_int(1.0f - g.w), a.w + CB + EPS);
        if (ub0 > thr || ub1 > thr || ub2 > thr || ub3 > thr) {
            int base = jbase + 4 * i;
            ins2(coarse_key(a.x, g.x), base + 0, v1, i1, v2, i2);
            ins2(coarse_key(a.y, g.y), base + 1, v1, i1, v2, i2);
            ins2(coarse_key(a.z, g.z), base + 2, v1, i1, v2, i2);
            ins2(coarse_key(a.w, g.w), base + 3, v1, i1, v2, i2);
            thr = fmaxf(thr, v2);
        }
    }

    __shared__ float s_v1[NTH]; __shared__ int s_i1[NTH];
    __shared__ float s_v2[NTH]; __shared__ int s_i2[NTH];
    s_v1[tid] = v1; s_i1[tid] = i1;
    s_v2[tid] = v2; s_i2[tid] = i2;
    __syncthreads();
    for (int s = NTH / 2; s > 0; s >>= 1) {
        if (tid < s) {
            float w1 = s_v1[tid + s], w2 = s_v2[tid + s];
            int   j1 = s_i1[tid + s], j2 = s_i2[tid + s];
            float a1 = s_v1[tid],     a2 = s_v2[tid];
            int   c1 = s_i1[tid],     c2 = s_i2[tid];
            top2_insert(w1, j1, a1, c1, a2, c2);
            top2_insert(w2, j2, a1, c1, a2, c2);
            s_v1[tid] = a1; s_i1[tid] = c1;
            s_v2[tid] = a2; s_i2[tid] = c2;
        }
        __syncthreads();
    }
    if (tid == 0) {
        g_part[blk] = make_int4(__float_as_int(s_v1[0]), s_i1[0],
                                __float_as_int(s_v2[0]), s_i2[0]);
    }
}

// ---------------------------------------------------------------------------
// K2: 8 tokens per block (grid 256).  shift/firstnz once per block from
// shared-cached rows; per-warp token finalize; batched gather.
// ---------------------------------------------------------------------------
__global__ void __launch_bounds__(NTH)
finish_kernel(const float* __restrict__ logits,
              const float* __restrict__ gu,
              const float* __restrict__ W,
              const int*   __restrict__ rwrt,
              const int*   __restrict__ psg_in,
              float*       __restrict__ out) {
    const int blk = blockIdx.x;          // 0..255
    const int t0  = blk * TPB;           // first token of this block
    const int b   = t0 / LL;
    const int tid = threadIdx.x;

    __shared__ int s_r[LL];
    __shared__ int s_p[LL];
    __shared__ int s_red[NTH];
    __shared__ int s_am[TPB];
    __shared__ int s_ps[TPB];

    const int* r = rwrt   + b * LL;
    const int* p = psg_in + b * LL;

    // cache rows in shared
    s_r[tid] = r[tid];  s_r[tid + NTH] = r[tid + NTH];
    s_p[tid] = p[tid];  s_p[tid + NTH] = p[tid + NTH];
    __syncthreads();

    // shift = sum(rwrt == 1) -- once per block
    s_red[tid] = (s_r[tid] == 1) + (s_r[tid + NTH] == 1);
    __syncthreads();
    for (int s = NTH / 2; s > 0; s >>= 1) {
        if (tid < s) s_red[tid] += s_red[tid + s];
        __syncthreads();
    }
    const int shift = s_red[0];
    __syncthreads();

    // firstnz = min l with trunc != 0 -- once per block
    int cand = LL;
#pragma unroll
    for (int k = 0; k < 2; k++) {
        int ll  = tid + k * NTH;
        int pos = ((ll - shift) % LL + LL) % LL;
        int fm  = 1 - s_r[LL - 1 - pos];
        int psv = (pos == 0) ? 1 : s_p[pos - 1];
        if (fm * psv != 0) cand = min(cand, ll);
    }
    s_red[tid] = cand;
    __syncthreads();
    for (int s = NTH / 2; s > 0; s >>= 1) {
        if (tid < s) s_red[tid] = min(s_red[tid], s_red[tid + s]);
        __syncthreads();
    }
    const int firstnz = s_red[0];

    // per-warp token finalize: warp w owns token t0+w
    const int w    = tid >> 5;
    const int lane = tid & 31;
    if (lane == 0) {
        const int t = t0 + w;
        const int l = t % LL;

        int pos   = ((l - shift) % LL + LL) % LL;
        int fm    = 1 - s_r[LL - 1 - pos];
        int psv   = (pos == 0) ? 1 : s_p[pos - 1];
        int trunc = fm * psv;
        s_ps[w] = (l >= firstnz) ? trunc : -1;

        float v1 = -INFINITY, v2 = -INFINITY;
        int   i1 = 0,         i2 = 1;
#pragma unroll
        for (int cc = 0; cc < CH; cc++) {
            int4 pr = g_part[t * CH + cc];
            top2_insert(__int_as_float(pr.x), pr.y, v1, i1, v2, i2);
            top2_insert(__int_as_float(pr.z), pr.w, v1, i1, v2, i2);
        }
        int win = i1;
        if (v1 - v2 < 0.02f) {
            double k1 = precise_key(logits[(size_t)t * VV + i1],
                                    gu[(size_t)t * VV + i1]);
            double k2 = precise_key(logits[(size_t)t * VV + i2],
                                    gu[(size_t)t * VV + i2]);
            if (k2 > k1 || (k2 == k1 && i2 < i1)) win = i2;
        }
        s_am[w] = win;
    }
    __syncthreads();

    // batched gather: 8 tokens x 192 float4 = 1536 slots, 6 iterations
    const float4* W4 = (const float4*)W;
#pragma unroll
    for (int it = 0; it < (TPB * ND4) / NTH; it++) {
        int idx = tid + it * NTH;        // 0..1535
        int tok = idx / ND4;             // 0..7
        int d   = idx - tok * ND4;       // 0..191
        int t   = t0 + tok;
        int l   = t % LL;

        int  am    = s_am[tok];
        int  psx   = s_ps[tok];
        bool use_a = (s_r[l] != 0) && (am < AVV);

        float4 acc = make_float4(0.f, 0.f, 0.f, 0.f);
        if (use_a) acc = W4[(size_t)am * ND4 + d];
        if (psx >= 0) {
            float4 wv = W4[(size_t)psx * ND4 + d];
            acc.x += wv.x; acc.y += wv.y; acc.z += wv.z; acc.w += wv.w;
        }
        ((float4*)out)[(size_t)t * ND4 + d] = acc;
    }
}

// ---------------------------------------------------------------------------
extern "C" void kernel_launch(void* const* d_in, const int* in_sizes, int n_in,
                              void* d_out, int out_size) {
    const float* logits = (const float*)d_in[0];
    const float* gu     = (const float*)d_in[1];
    const float* W      = (const float*)d_in[2];
    const int*   rwrt   = (const int*)d_in[3];
    const int*   psg    = (const int*)d_in[4];
    float* out = (float*)d_out;

    scan_kernel<<<NT * CH, NTH>>>(logits, gu);
    finish_kernel<<<NT / TPB, NTH>>>(logits, gu, W, rwrt, psg, out);
}